// round 14
// baseline (speedup 1.0000x reference)
#include <cuda_runtime.h>
#include <cuda_bf16.h>
#include <cstdint>

#define HH   16
#define DH   64
#define DD   1024
#define SMAX 4096

// Scratch (allocation-free rule: __device__ globals). Head-major [H][S][64].
__device__ float g_q[HH * SMAX * DH];
__device__ float g_k[HH * SMAX * DH];
__device__ float g_v[HH * SMAX * DH];
__device__ float g_ctx[HH * SMAX * DH];

// ===========================================================================
// Warp-level tensor core primitives (baseline PTX, works on compute_103)
// ===========================================================================
__device__ __forceinline__ uint32_t smem_u32(const void* p) {
    uint32_t a;
    asm("{ .reg .u64 t; cvta.to.shared.u64 t, %1; cvt.u32.u64 %0, t; }"
        : "=r"(a) : "l"(p));
    return a;
}

#define LDSM_X4(r0, r1, r2, r3, addr)                                        \
    asm volatile("ldmatrix.sync.aligned.m8n8.x4.shared.b16 {%0,%1,%2,%3}, [%4];" \
                 : "=r"(r0), "=r"(r1), "=r"(r2), "=r"(r3) : "r"(addr))

#define LDSM_X4_T(r0, r1, r2, r3, addr)                                      \
    asm volatile("ldmatrix.sync.aligned.m8n8.x4.trans.shared.b16 {%0,%1,%2,%3}, [%4];" \
                 : "=r"(r0), "=r"(r1), "=r"(r2), "=r"(r3) : "r"(addr))

#define MMA16816(d, a, b0, b1)                                               \
    asm volatile("mma.sync.aligned.m16n8k16.row.col.f32.bf16.bf16.f32 "     \
                 "{%0,%1,%2,%3}, {%4,%5,%6,%7}, {%8,%9}, {%0,%1,%2,%3};"    \
                 : "+f"((d)[0]), "+f"((d)[1]), "+f"((d)[2]), "+f"((d)[3])    \
                 : "r"((a)[0]), "r"((a)[1]), "r"((a)[2]), "r"((a)[3]),       \
                   "r"(b0), "r"(b1))

// Split float4 into bf16 hi + bf16 lo residual, packed as uint2 each.
__device__ __forceinline__ void split_bf16x3(float4 v, uint2& hv, uint2& lv) {
    __nv_bfloat162 h0 = __floats2bfloat162_rn(v.x, v.y);
    __nv_bfloat162 h1 = __floats2bfloat162_rn(v.z, v.w);
    float rx = v.x - __bfloat162float(h0.x);
    float ry = v.y - __bfloat162float(h0.y);
    float rz = v.z - __bfloat162float(h1.x);
    float rw = v.w - __bfloat162float(h1.y);
    __nv_bfloat162 l0 = __floats2bfloat162_rn(rx, ry);
    __nv_bfloat162 l1 = __floats2bfloat162_rn(rz, rw);
    hv = make_uint2(*reinterpret_cast<uint32_t*>(&h0),
                    *reinterpret_cast<uint32_t*>(&h1));
    lv = make_uint2(*reinterpret_cast<uint32_t*>(&l0),
                    *reinterpret_cast<uint32_t*>(&l1));
}

// ===========================================================================
// Tensor-core bf16x3 GEMM body (NT): C[M,N] = A[M,K] * B[N,K]^T + bias[N]
// 128x128 CTA tile, BK=32, 8 warps (2M x 4N), warp tile 64x32.
// Double-buffered smem, ONE __syncthreads per chunk:
//   MMA(buf p) -> convert+store chunk i+1 (buf 1-p) -> LDG chunk i+2 -> sync
// ===========================================================================
#define RS    40
#define TOFF  (128 * RS)               // elems per 128x32 tile
#define GBUF  (4 * TOFF)               // elems per buffer (Ah,Al,Bh,Bl)
#define GEMM_SMEM (2 * GBUF * 2)       // 81920 bytes

template<int A_HM, int C_HM>
__device__ __forceinline__ void gemm_dev(
    const float* __restrict__ A, const float* __restrict__ B,
    const float* __restrict__ bias, float* __restrict__ C,
    int N, int Kd, int S)
{
    extern __shared__ __nv_bfloat16 sh[];
    const uint32_t sb = smem_u32(sh);

    const int t    = threadIdx.x;
    const int lane = t & 31, wid = t >> 5;
    const int wm   = wid >> 2;
    const int wn   = wid & 3;
    const int m0   = blockIdx.y << 7, n0 = blockIdx.x << 7;

    const int lrow = t >> 3;
    const int lc4  = (t & 7) << 2;

    const int a_r  = wm * 64 + (lane & 15);
    const int a_c  = (lane >> 4) << 3;
    const int b_g  = lane >> 3;
    const int b_r  = wn * 32 + ((b_g >> 1) << 3) + (lane & 7);
    const int b_c  = (b_g & 1) << 3;

    float acc[4][4][4];
    #pragma unroll
    for (int i = 0; i < 4; i++)
        #pragma unroll
        for (int j = 0; j < 4; j++)
            #pragma unroll
            for (int r = 0; r < 4; r++) acc[i][j][r] = 0.0f;

    const int nch = Kd >> 5;

    float4 av[4], bv[4];

    // ---- helpers as lambdas ----
    auto ldg_chunk = [&](int k0) {
        #pragma unroll
        for (int u = 0; u < 4; u++) {
            int row = lrow + (u << 5);
            if (A_HM)
                av[u] = *(const float4*)(A + ((size_t)(k0 >> 6) * S + m0 + row) * DH
                                           + (k0 & 63) + lc4);
            else
                av[u] = *(const float4*)(A + (size_t)(m0 + row) * Kd + k0 + lc4);
            bv[u] = *(const float4*)(B + (size_t)(n0 + row) * Kd + k0 + lc4);
        }
    };
    auto store_chunk = [&](int p) {
        __nv_bfloat16* bp = sh + p * GBUF;
        #pragma unroll
        for (int u = 0; u < 4; u++) {
            int row = lrow + (u << 5);
            uint32_t eo = row * RS + lc4;
            uint2 hv, lv;
            split_bf16x3(av[u], hv, lv);
            *(uint2*)(bp + eo)            = hv;
            *(uint2*)(bp + TOFF + eo)     = lv;
            split_bf16x3(bv[u], hv, lv);
            *(uint2*)(bp + 2 * TOFF + eo) = hv;
            *(uint2*)(bp + 3 * TOFF + eo) = lv;
        }
    };

    // ---- prologue: chunk0 -> buf0; LDG chunk1 ----
    ldg_chunk(0);
    store_chunk(0);
    if (nch > 1) ldg_chunk(32);
    __syncthreads();

    for (int i = 0; i < nch; i++) {
        const int p = i & 1;
        const uint32_t base = sb + (uint32_t)p * (GBUF * 2);
        const uint32_t AH = base, AL = base + TOFF * 2,
                       BH = base + 2 * TOFF * 2, BL = base + 3 * TOFF * 2;

        // ---- MMA on buf p ----
        #pragma unroll
        for (int ks = 0; ks < 2; ks++) {
            const uint32_t acol = (a_c + (ks << 4)) << 1;
            const uint32_t bcol = (b_c + (ks << 4)) << 1;

            uint32_t aH[4][4], aL[4][4], bh[2][4], bl[2][4];
            #pragma unroll
            for (int mf = 0; mf < 4; mf++) {
                uint32_t ra = (uint32_t)(a_r + mf * 16) * (RS * 2);
                LDSM_X4(aH[mf][0], aH[mf][1], aH[mf][2], aH[mf][3], AH + ra + acol);
            }
            #pragma unroll
            for (int ng = 0; ng < 2; ng++) {
                uint32_t rb = (uint32_t)(b_r + ng * 16) * (RS * 2);
                LDSM_X4(bh[ng][0], bh[ng][1], bh[ng][2], bh[ng][3], BH + rb + bcol);
            }
            #pragma unroll
            for (int mf = 0; mf < 4; mf++)
                #pragma unroll
                for (int nf = 0; nf < 4; nf++) {
                    const uint32_t* b = bh[nf >> 1] + ((nf & 1) << 1);
                    MMA16816(acc[mf][nf], aH[mf], b[0], b[1]);
                }
            #pragma unroll
            for (int ng = 0; ng < 2; ng++) {
                uint32_t rb = (uint32_t)(b_r + ng * 16) * (RS * 2);
                LDSM_X4(bl[ng][0], bl[ng][1], bl[ng][2], bl[ng][3], BL + rb + bcol);
            }
            #pragma unroll
            for (int mf = 0; mf < 4; mf++)
                #pragma unroll
                for (int nf = 0; nf < 4; nf++) {
                    const uint32_t* b = bl[nf >> 1] + ((nf & 1) << 1);
                    MMA16816(acc[mf][nf], aH[mf], b[0], b[1]);
                }
            #pragma unroll
            for (int mf = 0; mf < 4; mf++) {
                uint32_t ra = (uint32_t)(a_r + mf * 16) * (RS * 2);
                LDSM_X4(aL[mf][0], aL[mf][1], aL[mf][2], aL[mf][3], AL + ra + acol);
            }
            #pragma unroll
            for (int mf = 0; mf < 4; mf++)
                #pragma unroll
                for (int nf = 0; nf < 4; nf++) {
                    const uint32_t* b = bh[nf >> 1] + ((nf & 1) << 1);
                    MMA16816(acc[mf][nf], aL[mf], b[0], b[1]);
                }
        }

        // ---- store prefetched chunk i+1 into buf 1-p; LDG chunk i+2 ----
        if (i + 1 < nch) {
            store_chunk(1 - p);
            if (i + 2 < nch) ldg_chunk((i + 2) << 5);
        }
        __syncthreads();
    }

    // ---- epilogue: fp32 + bias ----
    const int er = lane >> 2;
    const int ec = (lane & 3) << 1;
    #pragma unroll
    for (int mf = 0; mf < 4; mf++) {
        #pragma unroll
        for (int nf = 0; nf < 4; nf++) {
            int col  = n0 + wn * 32 + nf * 8 + ec;
            float bx = bias[col], by = bias[col + 1];
            int r0 = m0 + wm * 64 + mf * 16 + er;
            int r1 = r0 + 8;
            float2 o0 = make_float2(acc[mf][nf][0] + bx, acc[mf][nf][1] + by);
            float2 o1 = make_float2(acc[mf][nf][2] + bx, acc[mf][nf][3] + by);
            if (C_HM) {
                size_t base = (size_t)(col >> 6) * S;
                *(float2*)(C + (base + r0) * DH + (col & 63)) = o0;
                *(float2*)(C + (base + r1) * DH + (col & 63)) = o1;
            } else {
                *(float2*)(C + (size_t)r0 * N + col) = o0;
                *(float2*)(C + (size_t)r1 * N + col) = o1;
            }
        }
    }
}

// Fused Q/K/V projections: blockIdx.z selects the input/weight/output set.
__global__ __launch_bounds__(256) void gemm_qkv(
    const float* __restrict__ Xq, const float* __restrict__ Xk,
    const float* __restrict__ Xv,
    const float* __restrict__ Wq, const float* __restrict__ bq_,
    const float* __restrict__ Wk, const float* __restrict__ bk_,
    const float* __restrict__ Wv, const float* __restrict__ bv_,
    float* __restrict__ q, float* __restrict__ k, float* __restrict__ v,
    int N, int Kd, int S)
{
    const float *A, *B, *bias;
    float* C;
    if (blockIdx.z == 0)      { A = Xq; B = Wq; bias = bq_; C = q; }
    else if (blockIdx.z == 1) { A = Xk; B = Wk; bias = bk_; C = k; }
    else                      { A = Xv; B = Wv; bias = bv_; C = v; }
    gemm_dev<0, 1>(A, B, bias, C, N, Kd, S);
}

__global__ __launch_bounds__(256) void gemm_out(
    const float* __restrict__ A, const float* __restrict__ B,
    const float* __restrict__ bias, float* __restrict__ C,
    int N, int Kd, int S)
{
    gemm_dev<1, 0>(A, B, bias, C, N, Kd, S);
}

// ===========================================================================
// Tensor-core causal flash attention (bf16x3), double-buffered K/V staging.
// (unchanged from R13 — known-good)
// ===========================================================================
#define ARS   72
#define BUFE  18432
#define KHo   0
#define KLo   4608
#define VHo   9216
#define VLo   13824
#define QLoO  9216
#define ATTN_SMEM (2 * BUFE * 2)

__global__ __launch_bounds__(256) void attn_mma(
    const float* __restrict__ Q, const float* __restrict__ K,
    const float* __restrict__ V, float* __restrict__ O, int S)
{
    extern __shared__ __nv_bfloat16 sh[];
    const uint32_t sb = smem_u32(sh);

    const int h  = blockIdx.y;
    const int bq = gridDim.x - 1 - blockIdx.x;
    const int i0 = bq << 7;
    const float* Qh = Q + (size_t)h * S * DH;
    const float* Kh = K + (size_t)h * S * DH;
    const float* Vh = V + (size_t)h * S * DH;

    const int t = threadIdx.x, lane = t & 31, w = t >> 5;

    #pragma unroll
    for (int u = 0; u < 8; u++) {
        int idx = t + u * 256;
        int row = idx >> 4;
        int c4  = (idx & 15) << 2;
        float4 qv = *(const float4*)(Qh + (size_t)(i0 + row) * DH + c4);
        uint2 hv, lv;
        split_bf16x3(qv, hv, lv);
        *(uint2*)(sh + row * ARS + c4)        = hv;
        *(uint2*)(sh + QLoO + row * ARS + c4) = lv;
    }
    __syncthreads();

    uint32_t qhi[4][4], qlo[4][4];
    {
        const uint32_t ar = (uint32_t)(w * 16 + (lane & 15)) * (ARS * 2);
        const uint32_t ac = ((lane >> 4) << 3) * 2;
        #pragma unroll
        for (int ks = 0; ks < 4; ks++) {
            LDSM_X4(qhi[ks][0], qhi[ks][1], qhi[ks][2], qhi[ks][3],
                    sb + ar + ac + ks * 32);
            LDSM_X4(qlo[ks][0], qlo[ks][1], qlo[ks][2], qlo[ks][3],
                    sb + QLoO * 2 + ar + ac + ks * 32);
        }
    }

    float oacc[8][4];
    #pragma unroll
    for (int nf = 0; nf < 8; nf++)
        #pragma unroll
        for (int e = 0; e < 4; e++) oacc[nf][e] = 0.0f;
    float m0 = -1e30f, m1 = -1e30f, l0 = 0.0f, l1 = 0.0f;

    const int g    = lane >> 3;
    const uint32_t kb_r = ((g >> 1) << 3) + (lane & 7);
    const uint32_t kb_c = ((g & 1) << 3) * 2;
    const uint32_t vb_r = ((g & 1) << 3) + (lane & 7);
    const uint32_t vb_c = ((g >> 1) << 3) * 2;

    const int row_lo  = w * 16 + (lane >> 2);
    const int n_tiles = 2 * (bq + 1);

    const int lrow = t >> 4;
    const int lc4  = (t & 15) << 2;

    float4 kv4[4], vv4[4];
    #pragma unroll
    for (int u = 0; u < 4; u++) {
        int row = lrow + (u << 4);
        kv4[u] = *(const float4*)(Kh + (size_t)row * DH + lc4);
        vv4[u] = *(const float4*)(Vh + (size_t)row * DH + lc4);
    }
    __syncthreads();
    #pragma unroll
    for (int u = 0; u < 4; u++) {
        int row = lrow + (u << 4);
        uint2 hv, lv;
        split_bf16x3(kv4[u], hv, lv);
        *(uint2*)(sh + KHo + row * ARS + lc4) = hv;
        *(uint2*)(sh + KLo + row * ARS + lc4) = lv;
        split_bf16x3(vv4[u], hv, lv);
        *(uint2*)(sh + VHo + row * ARS + lc4) = hv;
        *(uint2*)(sh + VLo + row * ARS + lc4) = lv;
    }
    if (n_tiles > 1) {
        #pragma unroll
        for (int u = 0; u < 4; u++) {
            int row = 64 + lrow + (u << 4);
            kv4[u] = *(const float4*)(Kh + (size_t)row * DH + lc4);
            vv4[u] = *(const float4*)(Vh + (size_t)row * DH + lc4);
        }
    }
    __syncthreads();

    for (int jt = 0; jt < n_tiles; jt++) {
        const int j0   = jt << 6;
        const uint32_t bo = (uint32_t)(jt & 1) * (BUFE * 2);

        if (j0 <= i0 + w * 16 + 15) {
            float sacc[8][4];
            #pragma unroll
            for (int nf = 0; nf < 8; nf++)
                #pragma unroll
                for (int e = 0; e < 4; e++) sacc[nf][e] = 0.0f;

            #pragma unroll
            for (int ks = 0; ks < 4; ks++) {
                uint32_t kb[4][4];
                #pragma unroll
                for (int kg = 0; kg < 4; kg++)
                    LDSM_X4(kb[kg][0], kb[kg][1], kb[kg][2], kb[kg][3],
                            sb + bo + KHo * 2 + (kg * 16 + kb_r) * (ARS * 2) + ks * 32 + kb_c);
                #pragma unroll
                for (int nf = 0; nf < 8; nf++) {
                    const uint32_t* b = kb[nf >> 1] + ((nf & 1) << 1);
                    MMA16816(sacc[nf], qhi[ks], b[0], b[1]);
                }
                #pragma unroll
                for (int nf = 0; nf < 8; nf++) {
                    const uint32_t* b = kb[nf >> 1] + ((nf & 1) << 1);
                    MMA16816(sacc[nf], qlo[ks], b[0], b[1]);
                }
                #pragma unroll
                for (int kg = 0; kg < 4; kg++)
                    LDSM_X4(kb[kg][0], kb[kg][1], kb[kg][2], kb[kg][3],
                            sb + bo + KLo * 2 + (kg * 16 + kb_r) * (ARS * 2) + ks * 32 + kb_c);
                #pragma unroll
                for (int nf = 0; nf < 8; nf++) {
                    const uint32_t* b = kb[nf >> 1] + ((nf & 1) << 1);
                    MMA16816(sacc[nf], qhi[ks], b[0], b[1]);
                }
            }

            const bool needmask = (j0 + 63 > i0 + w * 16);
            #pragma unroll
            for (int nf = 0; nf < 8; nf++) {
                #pragma unroll
                for (int e = 0; e < 4; e++) {
                    float v = sacc[nf][e] * 0.125f;
                    if (needmask) {
                        int col = j0 + nf * 8 + ((lane & 3) << 1) + (e & 1);
                        int row = i0 + row_lo + ((e >> 1) << 3);
                        if (col > row) v = -1e30f;
                    }
                    sacc[nf][e] = v;
                }
            }
            float mt0 = -1e30f, mt1 = -1e30f;
            #pragma unroll
            for (int nf = 0; nf < 8; nf++) {
                mt0 = fmaxf(mt0, fmaxf(sacc[nf][0], sacc[nf][1]));
                mt1 = fmaxf(mt1, fmaxf(sacc[nf][2], sacc[nf][3]));
            }
            mt0 = fmaxf(mt0, __shfl_xor_sync(0xffffffffu, mt0, 1));
            mt0 = fmaxf(mt0, __shfl_xor_sync(0xffffffffu, mt0, 2));
            mt1 = fmaxf(mt1, __shfl_xor_sync(0xffffffffu, mt1, 1));
            mt1 = fmaxf(mt1, __shfl_xor_sync(0xffffffffu, mt1, 2));

            float mn0 = fmaxf(m0, mt0), mn1 = fmaxf(m1, mt1);
            float a0 = __expf(m0 - mn0), a1 = __expf(m1 - mn1);
            m0 = mn0; m1 = mn1;

            float s0 = 0.0f, s1 = 0.0f;
            #pragma unroll
            for (int nf = 0; nf < 8; nf++) {
                sacc[nf][0] = __expf(sacc[nf][0] - m0);
                sacc[nf][1] = __expf(sacc[nf][1] - m0);
                sacc[nf][2] = __expf(sacc[nf][2] - m1);
                sacc[nf][3] = __expf(sacc[nf][3] - m1);
                s0 += sacc[nf][0] + sacc[nf][1];
                s1 += sacc[nf][2] + sacc[nf][3];
            }
            s0 += __shfl_xor_sync(0xffffffffu, s0, 1);
            s0 += __shfl_xor_sync(0xffffffffu, s0, 2);
            s1 += __shfl_xor_sync(0xffffffffu, s1, 1);
            s1 += __shfl_xor_sync(0xffffffffu, s1, 2);
            l0 = l0 * a0 + s0;
            l1 = l1 * a1 + s1;
            #pragma unroll
            for (int nf = 0; nf < 8; nf++) {
                oacc[nf][0] *= a0; oacc[nf][1] *= a0;
                oacc[nf][2] *= a1; oacc[nf][3] *= a1;
            }

            #pragma unroll
            for (int ks = 0; ks < 4; ks++) {
                uint32_t phi[4], plo[4];
                #pragma unroll
                for (int half = 0; half < 2; half++) {
                    const float* p = sacc[2 * ks + half];
                    __nv_bfloat162 h01 = __floats2bfloat162_rn(p[0], p[1]);
                    __nv_bfloat162 h23 = __floats2bfloat162_rn(p[2], p[3]);
                    __nv_bfloat162 l01 = __floats2bfloat162_rn(
                        p[0] - __bfloat162float(h01.x), p[1] - __bfloat162float(h01.y));
                    __nv_bfloat162 l23 = __floats2bfloat162_rn(
                        p[2] - __bfloat162float(h23.x), p[3] - __bfloat162float(h23.y));
                    phi[half * 2 + 0] = *reinterpret_cast<uint32_t*>(&h01);
                    phi[half * 2 + 1] = *reinterpret_cast<uint32_t*>(&h23);
                    plo[half * 2 + 0] = *reinterpret_cast<uint32_t*>(&l01);
                    plo[half * 2 + 1] = *reinterpret_cast<uint32_t*>(&l23);
                }
                uint32_t vb[4][4];
                #pragma unroll
                for (int kg = 0; kg < 4; kg++)
                    LDSM_X4_T(vb[kg][0], vb[kg][1], vb[kg][2], vb[kg][3],
                              sb + bo + VHo * 2 + (ks * 16 + vb_r) * (ARS * 2) + kg * 32 + vb_c);
                #pragma unroll
                for (int nf = 0; nf < 8; nf++) {
                    const uint32_t* b = vb[nf >> 1] + ((nf & 1) << 1);
                    MMA16816(oacc[nf], phi, b[0], b[1]);
                }
                #pragma unroll
                for (int nf = 0; nf < 8; nf++) {
                    const uint32_t* b = vb[nf >> 1] + ((nf & 1) << 1);
                    MMA16816(oacc[nf], plo, b[0], b[1]);
                }
                #pragma unroll
                for (int kg = 0; kg < 4; kg++)
                    LDSM_X4_T(vb[kg][0], vb[kg][1], vb[kg][2], vb[kg][3],
                              sb + bo + VLo * 2 + (ks * 16 + vb_r) * (ARS * 2) + kg * 32 + vb_c);
                #pragma unroll
                for (int nf = 0; nf < 8; nf++) {
                    const uint32_t* b = vb[nf >> 1] + ((nf & 1) << 1);
                    MMA16816(oacc[nf], phi, b[0], b[1]);
                }
            }
        }

        if (jt + 1 < n_tiles) {
            __nv_bfloat16* dst = sh + ((jt + 1) & 1) * BUFE;
            #pragma unroll
            for (int u = 0; u < 4; u++) {
                int row = lrow + (u << 4);
                uint2 hv, lv;
                split_bf16x3(kv4[u], hv, lv);
                *(uint2*)(dst + KHo + row * ARS + lc4) = hv;
                *(uint2*)(dst + KLo + row * ARS + lc4) = lv;
                split_bf16x3(vv4[u], hv, lv);
                *(uint2*)(dst + VHo + row * ARS + lc4) = hv;
                *(uint2*)(dst + VLo + row * ARS + lc4) = lv;
            }
            if (jt + 2 < n_tiles) {
                const int jn = (jt + 2) << 6;
                #pragma unroll
                for (int u = 0; u < 4; u++) {
                    int row = jn + lrow + (u << 4);
                    kv4[u] = *(const float4*)(Kh + (size_t)row * DH + lc4);
                    vv4[u] = *(const float4*)(Vh + (size_t)row * DH + lc4);
                }
            }
        }
        __syncthreads();
    }

    const float inv0 = 1.0f / l0, inv1 = 1.0f / l1;
    const int r0 = i0 + row_lo;
    #pragma unroll
    for (int nf = 0; nf < 8; nf++) {
        int col = nf * 8 + ((lane & 3) << 1);
        *(float2*)(O + ((size_t)h * S + r0) * DH + col) =
            make_float2(oacc[nf][0] * inv0, oacc[nf][1] * inv0);
        *(float2*)(O + ((size_t)h * S + r0 + 8) * DH + col) =
            make_float2(oacc[nf][2] * inv1, oacc[nf][3] * inv1);
    }
}

// ---------------------------------------------------------------------------
extern "C" void kernel_launch(void* const* d_in, const int* in_sizes, int n_in,
                              void* d_out, int out_size)
{
    const float* Xq = (const float*)d_in[0];
    const float* Xk = (const float*)d_in[1];
    const float* Xv = (const float*)d_in[2];
    const float* Wq = (const float*)d_in[3];
    const float* bq = (const float*)d_in[4];
    const float* Wk = (const float*)d_in[5];
    const float* bk = (const float*)d_in[6];
    const float* Wv = (const float*)d_in[7];
    const float* bv = (const float*)d_in[8];
    const float* Wo = (const float*)d_in[9];
    const float* bo = (const float*)d_in[10];
    float* out = (float*)d_out;

    const int S = in_sizes[0] / DD;   // 4096

    float *q, *k, *v, *ctx;
    cudaGetSymbolAddress((void**)&q,   g_q);
    cudaGetSymbolAddress((void**)&k,   g_k);
    cudaGetSymbolAddress((void**)&v,   g_v);
    cudaGetSymbolAddress((void**)&ctx, g_ctx);

    cudaFuncSetAttribute(gemm_qkv,
                         cudaFuncAttributeMaxDynamicSharedMemorySize, GEMM_SMEM);
    cudaFuncSetAttribute(gemm_out,
                         cudaFuncAttributeMaxDynamicSharedMemorySize, GEMM_SMEM);
    cudaFuncSetAttribute(attn_mma,
                         cudaFuncAttributeMaxDynamicSharedMemorySize, ATTN_SMEM);

    gemm_qkv<<<dim3(DD / 128, S / 128, 3), 256, GEMM_SMEM>>>(
        Xq, Xk, Xv, Wq, bq, Wk, bk, Wv, bv, q, k, v, DD, DD, S);

    attn_mma<<<dim3(S / 128, HH), 256, ATTN_SMEM>>>(q, k, v, ctx, S);

    gemm_out<<<dim3(DD / 128, S / 128), 256, GEMM_SMEM>>>(ctx, Wo, bo, out, DD, DD, S);
}

// round 15
// speedup vs baseline: 1.4114x; 1.4114x over previous
#include <cuda_runtime.h>
#include <cuda_fp16.h>
#include <cstdint>

#define HH   16
#define DH   64
#define DD   1024
#define SMAX 4096

// Scratch (allocation-free rule: __device__ globals). Head-major [H][S][64].
__device__ float g_q[HH * SMAX * DH];
__device__ float g_k[HH * SMAX * DH];
__device__ float g_v[HH * SMAX * DH];
__device__ float g_ctx[HH * SMAX * DH];

// ===========================================================================
// Warp-level tensor core primitives (baseline PTX, works on compute_103)
// ===========================================================================
__device__ __forceinline__ uint32_t smem_u32(const void* p) {
    uint32_t a;
    asm("{ .reg .u64 t; cvta.to.shared.u64 t, %1; cvt.u32.u64 %0, t; }"
        : "=r"(a) : "l"(p));
    return a;
}

#define LDSM_X4(r0, r1, r2, r3, addr)                                        \
    asm volatile("ldmatrix.sync.aligned.m8n8.x4.shared.b16 {%0,%1,%2,%3}, [%4];" \
                 : "=r"(r0), "=r"(r1), "=r"(r2), "=r"(r3) : "r"(addr))

#define LDSM_X4_T(r0, r1, r2, r3, addr)                                      \
    asm volatile("ldmatrix.sync.aligned.m8n8.x4.trans.shared.b16 {%0,%1,%2,%3}, [%4];" \
                 : "=r"(r0), "=r"(r1), "=r"(r2), "=r"(r3) : "r"(addr))

#define MMA16816(d, a, b0, b1)                                               \
    asm volatile("mma.sync.aligned.m16n8k16.row.col.f32.f16.f16.f32 "      \
                 "{%0,%1,%2,%3}, {%4,%5,%6,%7}, {%8,%9}, {%0,%1,%2,%3};"    \
                 : "+f"((d)[0]), "+f"((d)[1]), "+f"((d)[2]), "+f"((d)[3])    \
                 : "r"((a)[0]), "r"((a)[1]), "r"((a)[2]), "r"((a)[3]),       \
                   "r"(b0), "r"(b1))

// fp16 hi conversion only
__device__ __forceinline__ uint2 cvt_f16(float4 v) {
    __half2 h0 = __floats2half2_rn(v.x, v.y);
    __half2 h1 = __floats2half2_rn(v.z, v.w);
    return make_uint2(*reinterpret_cast<uint32_t*>(&h0),
                      *reinterpret_cast<uint32_t*>(&h1));
}

// Split float4 into fp16 hi + fp16 lo residual, packed as uint2 each.
__device__ __forceinline__ void split_f16x2(float4 v, uint2& hv, uint2& lv) {
    __half2 h0 = __floats2half2_rn(v.x, v.y);
    __half2 h1 = __floats2half2_rn(v.z, v.w);
    float rx = v.x - __low2float(h0);
    float ry = v.y - __high2float(h0);
    float rz = v.z - __low2float(h1);
    float rw = v.w - __high2float(h1);
    __half2 l0 = __floats2half2_rn(rx, ry);
    __half2 l1 = __floats2half2_rn(rz, rw);
    hv = make_uint2(*reinterpret_cast<uint32_t*>(&h0),
                    *reinterpret_cast<uint32_t*>(&h1));
    lv = make_uint2(*reinterpret_cast<uint32_t*>(&l0),
                    *reinterpret_cast<uint32_t*>(&l1));
}

// ===========================================================================
// Tensor-core fp16x2 GEMM (NT): C[M,N] = (Ah+Al) * Bh^T + bias[N]
// 128x128 CTA tile, BK=32, 8 warps (2M x 4N), warp tile 64x32.
// R13 loop structure (2 syncs/chunk — the measured-best schedule).
// Smem: Ah, Al, Bh tiles only (weights lo dropped; error ~2^-11).
// ===========================================================================
#define RS    40
#define TOFF  (128 * RS)

template<int A_HM, int C_HM>
__device__ __forceinline__ void gemm_dev(
    const float* __restrict__ A, const float* __restrict__ B,
    const float* __restrict__ bias, float* __restrict__ C,
    int N, int Kd, int S)
{
    __shared__ __half sh[3 * TOFF];   // Ah, Al, Bh = 30720 B
    const uint32_t sb = smem_u32(sh);
    const uint32_t AH = sb, AL = sb + TOFF * 2, BH = sb + 2 * TOFF * 2;

    const int t    = threadIdx.x;
    const int lane = t & 31, wid = t >> 5;
    const int wm   = wid >> 2;
    const int wn   = wid & 3;
    const int m0   = blockIdx.y << 7, n0 = blockIdx.x << 7;

    const int lrow = t >> 3;
    const int lc4  = (t & 7) << 2;

    const int a_r  = wm * 64 + (lane & 15);
    const int a_c  = (lane >> 4) << 3;
    const int b_g  = lane >> 3;
    const int b_r  = wn * 32 + ((b_g >> 1) << 3) + (lane & 7);
    const int b_c  = (b_g & 1) << 3;

    float acc[4][4][4];
    #pragma unroll
    for (int i = 0; i < 4; i++)
        #pragma unroll
        for (int j = 0; j < 4; j++)
            #pragma unroll
            for (int r = 0; r < 4; r++) acc[i][j][r] = 0.0f;

    const int nch = Kd >> 5;

    float4 av[4], bv[4];
    #pragma unroll
    for (int u = 0; u < 4; u++) {
        int row = lrow + (u << 5);
        if (A_HM)
            av[u] = *(const float4*)(A + (size_t)(m0 + row) * DH + lc4);
        else
            av[u] = *(const float4*)(A + (size_t)(m0 + row) * Kd + lc4);
        bv[u] = *(const float4*)(B + (size_t)(n0 + row) * Kd + lc4);
    }

    for (int i = 0; i < nch; i++) {
        __syncthreads();
        #pragma unroll
        for (int u = 0; u < 4; u++) {
            int row = lrow + (u << 5);
            uint32_t eo = row * RS + lc4;
            uint2 hv, lv;
            split_f16x2(av[u], hv, lv);
            *(uint2*)(sh + eo)            = hv;
            *(uint2*)(sh + TOFF + eo)     = lv;
            *(uint2*)(sh + 2 * TOFF + eo) = cvt_f16(bv[u]);
        }
        __syncthreads();

        if (i + 1 < nch) {
            const int k0 = (i + 1) << 5;
            #pragma unroll
            for (int u = 0; u < 4; u++) {
                int row = lrow + (u << 5);
                if (A_HM)
                    av[u] = *(const float4*)(A + ((size_t)(k0 >> 6) * S + m0 + row) * DH
                                               + (k0 & 63) + lc4);
                else
                    av[u] = *(const float4*)(A + (size_t)(m0 + row) * Kd + k0 + lc4);
                bv[u] = *(const float4*)(B + (size_t)(n0 + row) * Kd + k0 + lc4);
            }
        }

        #pragma unroll
        for (int ks = 0; ks < 2; ks++) {
            const uint32_t acol = (a_c + (ks << 4)) << 1;
            const uint32_t bcol = (b_c + (ks << 4)) << 1;

            uint32_t aH[4][4], aL[4][4], bh[2][4];
            #pragma unroll
            for (int mf = 0; mf < 4; mf++) {
                uint32_t ra = (uint32_t)(a_r + mf * 16) * (RS * 2);
                LDSM_X4(aH[mf][0], aH[mf][1], aH[mf][2], aH[mf][3], AH + ra + acol);
            }
            #pragma unroll
            for (int ng = 0; ng < 2; ng++) {
                uint32_t rb = (uint32_t)(b_r + ng * 16) * (RS * 2);
                LDSM_X4(bh[ng][0], bh[ng][1], bh[ng][2], bh[ng][3], BH + rb + bcol);
            }
            #pragma unroll
            for (int mf = 0; mf < 4; mf++)
                #pragma unroll
                for (int nf = 0; nf < 4; nf++) {
                    const uint32_t* b = bh[nf >> 1] + ((nf & 1) << 1);
                    MMA16816(acc[mf][nf], aH[mf], b[0], b[1]);
                }
            #pragma unroll
            for (int mf = 0; mf < 4; mf++) {
                uint32_t ra = (uint32_t)(a_r + mf * 16) * (RS * 2);
                LDSM_X4(aL[mf][0], aL[mf][1], aL[mf][2], aL[mf][3], AL + ra + acol);
            }
            #pragma unroll
            for (int mf = 0; mf < 4; mf++)
                #pragma unroll
                for (int nf = 0; nf < 4; nf++) {
                    const uint32_t* b = bh[nf >> 1] + ((nf & 1) << 1);
                    MMA16816(acc[mf][nf], aL[mf], b[0], b[1]);
                }
        }
    }

    const int er = lane >> 2;
    const int ec = (lane & 3) << 1;
    #pragma unroll
    for (int mf = 0; mf < 4; mf++) {
        #pragma unroll
        for (int nf = 0; nf < 4; nf++) {
            int col  = n0 + wn * 32 + nf * 8 + ec;
            float bx = bias[col], by = bias[col + 1];
            int r0 = m0 + wm * 64 + mf * 16 + er;
            int r1 = r0 + 8;
            float2 o0 = make_float2(acc[mf][nf][0] + bx, acc[mf][nf][1] + by);
            float2 o1 = make_float2(acc[mf][nf][2] + bx, acc[mf][nf][3] + by);
            if (C_HM) {
                size_t base = (size_t)(col >> 6) * S;
                *(float2*)(C + (base + r0) * DH + (col & 63)) = o0;
                *(float2*)(C + (base + r1) * DH + (col & 63)) = o1;
            } else {
                *(float2*)(C + (size_t)r0 * N + col) = o0;
                *(float2*)(C + (size_t)r1 * N + col) = o1;
            }
        }
    }
}

// Fused Q/K/V projections: blockIdx.z selects the input/weight/output set.
__global__ __launch_bounds__(256) void gemm_qkv(
    const float* __restrict__ Xq, const float* __restrict__ Xk,
    const float* __restrict__ Xv,
    const float* __restrict__ Wq, const float* __restrict__ bq_,
    const float* __restrict__ Wk, const float* __restrict__ bk_,
    const float* __restrict__ Wv, const float* __restrict__ bv_,
    float* __restrict__ q, float* __restrict__ k, float* __restrict__ v,
    int N, int Kd, int S)
{
    const float *A, *B, *bias;
    float* C;
    if (blockIdx.z == 0)      { A = Xq; B = Wq; bias = bq_; C = q; }
    else if (blockIdx.z == 1) { A = Xk; B = Wk; bias = bk_; C = k; }
    else                      { A = Xv; B = Wv; bias = bv_; C = v; }
    gemm_dev<0, 1>(A, B, bias, C, N, Kd, S);
}

__global__ __launch_bounds__(256) void gemm_out(
    const float* __restrict__ A, const float* __restrict__ B,
    const float* __restrict__ bias, float* __restrict__ C,
    int N, int Kd, int S)
{
    gemm_dev<1, 0>(A, B, bias, C, N, Kd, S);
}

// ===========================================================================
// Tensor-core causal flash attention (fp16x2), double-buffered K/V staging.
// One CTA = (head, 128 q rows), 8 warps, warp w owns rows [w*16, w*16+16).
// Q hi/lo in registers; K, V stored hi-only in smem (error ~2^-11).
// QK = QhKh + QlKh;  PV = PhVh + PlVh (P hi/lo built in registers).
// ===========================================================================
#define ARS   72
#define BUFE  9216             // fp16 elems per K/V buffer (Kh 4608 + Vh 4608)
#define KHo   0
#define VHo   4608
#define QLoO  9216             // Q lo (Q hi at 0) during staging
#define ATTN_SMEM (2 * BUFE * 2)   // 36864 bytes

__global__ __launch_bounds__(256) void attn_mma(
    const float* __restrict__ Q, const float* __restrict__ K,
    const float* __restrict__ V, float* __restrict__ O, int S)
{
    extern __shared__ __half sh[];
    const uint32_t sb = smem_u32(sh);

    const int h  = blockIdx.y;
    const int bq = gridDim.x - 1 - blockIdx.x;   // longest CTAs first
    const int i0 = bq << 7;
    const float* Qh = Q + (size_t)h * S * DH;
    const float* Kh = K + (size_t)h * S * DH;
    const float* Vh = V + (size_t)h * S * DH;

    const int t = threadIdx.x, lane = t & 31, w = t >> 5;

    // ---- stage Q (128x64) as hi/lo fp16 ----
    #pragma unroll
    for (int u = 0; u < 8; u++) {
        int idx = t + u * 256;
        int row = idx >> 4;
        int c4  = (idx & 15) << 2;
        float4 qv = *(const float4*)(Qh + (size_t)(i0 + row) * DH + c4);
        uint2 hv, lv;
        split_f16x2(qv, hv, lv);
        *(uint2*)(sh + row * ARS + c4)        = hv;
        *(uint2*)(sh + QLoO + row * ARS + c4) = lv;
    }
    __syncthreads();

    // ---- Q fragments (registers for the whole kernel) ----
    uint32_t qhi[4][4], qlo[4][4];
    {
        const uint32_t ar = (uint32_t)(w * 16 + (lane & 15)) * (ARS * 2);
        const uint32_t ac = ((lane >> 4) << 3) * 2;
        #pragma unroll
        for (int ks = 0; ks < 4; ks++) {
            LDSM_X4(qhi[ks][0], qhi[ks][1], qhi[ks][2], qhi[ks][3],
                    sb + ar + ac + ks * 32);
            LDSM_X4(qlo[ks][0], qlo[ks][1], qlo[ks][2], qlo[ks][3],
                    sb + QLoO * 2 + ar + ac + ks * 32);
        }
    }

    float oacc[8][4];
    #pragma unroll
    for (int nf = 0; nf < 8; nf++)
        #pragma unroll
        for (int e = 0; e < 4; e++) oacc[nf][e] = 0.0f;
    float m0 = -1e30f, m1 = -1e30f, l0 = 0.0f, l1 = 0.0f;

    const int g    = lane >> 3;
    const uint32_t kb_r = ((g >> 1) << 3) + (lane & 7);
    const uint32_t kb_c = ((g & 1) << 3) * 2;
    const uint32_t vb_r = ((g & 1) << 3) + (lane & 7);
    const uint32_t vb_c = ((g >> 1) << 3) * 2;

    const int row_lo  = w * 16 + (lane >> 2);
    const int n_tiles = 2 * (bq + 1);

    const int lrow = t >> 4;
    const int lc4  = (t & 15) << 2;

    // ---- prologue: LDG tile0; sync (Q frags consumed); store; LDG tile1 ----
    float4 kv4[4], vv4[4];
    #pragma unroll
    for (int u = 0; u < 4; u++) {
        int row = lrow + (u << 4);
        kv4[u] = *(const float4*)(Kh + (size_t)row * DH + lc4);
        vv4[u] = *(const float4*)(Vh + (size_t)row * DH + lc4);
    }
    __syncthreads();
    #pragma unroll
    for (int u = 0; u < 4; u++) {
        int row = lrow + (u << 4);
        *(uint2*)(sh + KHo + row * ARS + lc4) = cvt_f16(kv4[u]);
        *(uint2*)(sh + VHo + row * ARS + lc4) = cvt_f16(vv4[u]);
    }
    if (n_tiles > 1) {
        #pragma unroll
        for (int u = 0; u < 4; u++) {
            int row = 64 + lrow + (u << 4);
            kv4[u] = *(const float4*)(Kh + (size_t)row * DH + lc4);
            vv4[u] = *(const float4*)(Vh + (size_t)row * DH + lc4);
        }
    }
    __syncthreads();

    for (int jt = 0; jt < n_tiles; jt++) {
        const int j0   = jt << 6;
        const uint32_t bo = (uint32_t)(jt & 1) * (BUFE * 2);

        if (j0 <= i0 + w * 16 + 15) {
            // ---- S = Q K^T (fp16x2, 2 passes) ----
            float sacc[8][4];
            #pragma unroll
            for (int nf = 0; nf < 8; nf++)
                #pragma unroll
                for (int e = 0; e < 4; e++) sacc[nf][e] = 0.0f;

            #pragma unroll
            for (int ks = 0; ks < 4; ks++) {
                uint32_t kb[4][4];
                #pragma unroll
                for (int kg = 0; kg < 4; kg++)
                    LDSM_X4(kb[kg][0], kb[kg][1], kb[kg][2], kb[kg][3],
                            sb + bo + KHo * 2 + (kg * 16 + kb_r) * (ARS * 2) + ks * 32 + kb_c);
                #pragma unroll
                for (int nf = 0; nf < 8; nf++) {
                    const uint32_t* b = kb[nf >> 1] + ((nf & 1) << 1);
                    MMA16816(sacc[nf], qhi[ks], b[0], b[1]);
                }
                #pragma unroll
                for (int nf = 0; nf < 8; nf++) {
                    const uint32_t* b = kb[nf >> 1] + ((nf & 1) << 1);
                    MMA16816(sacc[nf], qlo[ks], b[0], b[1]);
                }
            }

            // ---- softmax update ----
            const bool needmask = (j0 + 63 > i0 + w * 16);
            #pragma unroll
            for (int nf = 0; nf < 8; nf++) {
                #pragma unroll
                for (int e = 0; e < 4; e++) {
                    float v = sacc[nf][e] * 0.125f;
                    if (needmask) {
                        int col = j0 + nf * 8 + ((lane & 3) << 1) + (e & 1);
                        int row = i0 + row_lo + ((e >> 1) << 3);
                        if (col > row) v = -1e30f;
                    }
                    sacc[nf][e] = v;
                }
            }
            float mt0 = -1e30f, mt1 = -1e30f;
            #pragma unroll
            for (int nf = 0; nf < 8; nf++) {
                mt0 = fmaxf(mt0, fmaxf(sacc[nf][0], sacc[nf][1]));
                mt1 = fmaxf(mt1, fmaxf(sacc[nf][2], sacc[nf][3]));
            }
            mt0 = fmaxf(mt0, __shfl_xor_sync(0xffffffffu, mt0, 1));
            mt0 = fmaxf(mt0, __shfl_xor_sync(0xffffffffu, mt0, 2));
            mt1 = fmaxf(mt1, __shfl_xor_sync(0xffffffffu, mt1, 1));
            mt1 = fmaxf(mt1, __shfl_xor_sync(0xffffffffu, mt1, 2));

            float mn0 = fmaxf(m0, mt0), mn1 = fmaxf(m1, mt1);
            float a0 = __expf(m0 - mn0), a1 = __expf(m1 - mn1);
            m0 = mn0; m1 = mn1;

            float s0 = 0.0f, s1 = 0.0f;
            #pragma unroll
            for (int nf = 0; nf < 8; nf++) {
                sacc[nf][0] = __expf(sacc[nf][0] - m0);
                sacc[nf][1] = __expf(sacc[nf][1] - m0);
                sacc[nf][2] = __expf(sacc[nf][2] - m1);
                sacc[nf][3] = __expf(sacc[nf][3] - m1);
                s0 += sacc[nf][0] + sacc[nf][1];
                s1 += sacc[nf][2] + sacc[nf][3];
            }
            s0 += __shfl_xor_sync(0xffffffffu, s0, 1);
            s0 += __shfl_xor_sync(0xffffffffu, s0, 2);
            s1 += __shfl_xor_sync(0xffffffffu, s1, 1);
            s1 += __shfl_xor_sync(0xffffffffu, s1, 2);
            l0 = l0 * a0 + s0;
            l1 = l1 * a1 + s1;
            #pragma unroll
            for (int nf = 0; nf < 8; nf++) {
                oacc[nf][0] *= a0; oacc[nf][1] *= a0;
                oacc[nf][2] *= a1; oacc[nf][3] *= a1;
            }

            // ---- O += P V (fp16x2; P hi/lo frags straight from registers) ----
            #pragma unroll
            for (int ks = 0; ks < 4; ks++) {
                uint32_t phi[4], plo[4];
                #pragma unroll
                for (int half = 0; half < 2; half++) {
                    const float* p = sacc[2 * ks + half];
                    __half2 h01 = __floats2half2_rn(p[0], p[1]);
                    __half2 h23 = __floats2half2_rn(p[2], p[3]);
                    __half2 l01 = __floats2half2_rn(
                        p[0] - __low2float(h01), p[1] - __high2float(h01));
                    __half2 l23 = __floats2half2_rn(
                        p[2] - __low2float(h23), p[3] - __high2float(h23));
                    phi[half * 2 + 0] = *reinterpret_cast<uint32_t*>(&h01);
                    phi[half * 2 + 1] = *reinterpret_cast<uint32_t*>(&h23);
                    plo[half * 2 + 0] = *reinterpret_cast<uint32_t*>(&l01);
                    plo[half * 2 + 1] = *reinterpret_cast<uint32_t*>(&l23);
                }
                uint32_t vb[4][4];
                #pragma unroll
                for (int kg = 0; kg < 4; kg++)
                    LDSM_X4_T(vb[kg][0], vb[kg][1], vb[kg][2], vb[kg][3],
                              sb + bo + VHo * 2 + (ks * 16 + vb_r) * (ARS * 2) + kg * 32 + vb_c);
                #pragma unroll
                for (int nf = 0; nf < 8; nf++) {
                    const uint32_t* b = vb[nf >> 1] + ((nf & 1) << 1);
                    MMA16816(oacc[nf], phi, b[0], b[1]);
                }
                #pragma unroll
                for (int nf = 0; nf < 8; nf++) {
                    const uint32_t* b = vb[nf >> 1] + ((nf & 1) << 1);
                    MMA16816(oacc[nf], plo, b[0], b[1]);
                }
            }
        }

        // ---- stage tile jt+1 (regs -> buf[(jt+1)&1]); LDG tile jt+2 ----
        if (jt + 1 < n_tiles) {
            __half* dst = sh + ((jt + 1) & 1) * BUFE;
            #pragma unroll
            for (int u = 0; u < 4; u++) {
                int row = lrow + (u << 4);
                *(uint2*)(dst + KHo + row * ARS + lc4) = cvt_f16(kv4[u]);
                *(uint2*)(dst + VHo + row * ARS + lc4) = cvt_f16(vv4[u]);
            }
            if (jt + 2 < n_tiles) {
                const int jn = (jt + 2) << 6;
                #pragma unroll
                for (int u = 0; u < 4; u++) {
                    int row = jn + lrow + (u << 4);
                    kv4[u] = *(const float4*)(Kh + (size_t)row * DH + lc4);
                    vv4[u] = *(const float4*)(Vh + (size_t)row * DH + lc4);
                }
            }
        }
        __syncthreads();
    }

    // ---- normalize + store ----
    const float inv0 = 1.0f / l0, inv1 = 1.0f / l1;
    const int r0 = i0 + row_lo;
    #pragma unroll
    for (int nf = 0; nf < 8; nf++) {
        int col = nf * 8 + ((lane & 3) << 1);
        *(float2*)(O + ((size_t)h * S + r0) * DH + col) =
            make_float2(oacc[nf][0] * inv0, oacc[nf][1] * inv0);
        *(float2*)(O + ((size_t)h * S + r0 + 8) * DH + col) =
            make_float2(oacc[nf][2] * inv1, oacc[nf][3] * inv1);
    }
}

// ---------------------------------------------------------------------------
extern "C" void kernel_launch(void* const* d_in, const int* in_sizes, int n_in,
                              void* d_out, int out_size)
{
    const float* Xq = (const float*)d_in[0];
    const float* Xk = (const float*)d_in[1];
    const float* Xv = (const float*)d_in[2];
    const float* Wq = (const float*)d_in[3];
    const float* bq = (const float*)d_in[4];
    const float* Wk = (const float*)d_in[5];
    const float* bk = (const float*)d_in[6];
    const float* Wv = (const float*)d_in[7];
    const float* bv = (const float*)d_in[8];
    const float* Wo = (const float*)d_in[9];
    const float* bo = (const float*)d_in[10];
    float* out = (float*)d_out;

    const int S = in_sizes[0] / DD;   // 4096

    float *q, *k, *v, *ctx;
    cudaGetSymbolAddress((void**)&q,   g_q);
    cudaGetSymbolAddress((void**)&k,   g_k);
    cudaGetSymbolAddress((void**)&v,   g_v);
    cudaGetSymbolAddress((void**)&ctx, g_ctx);

    cudaFuncSetAttribute(attn_mma,
                         cudaFuncAttributeMaxDynamicSharedMemorySize, ATTN_SMEM);

    gemm_qkv<<<dim3(DD / 128, S / 128, 3), 256>>>(
        Xq, Xk, Xv, Wq, bq, Wk, bk, Wv, bv, q, k, v, DD, DD, S);

    attn_mma<<<dim3(S / 128, HH), 256, ATTN_SMEM>>>(q, k, v, ctx, S);

    gemm_out<<<dim3(DD / 128, S / 128), 256>>>(ctx, Wo, bo, out, DD, DD, S);
}